// round 14
// baseline (speedup 1.0000x reference)
#include <cuda_runtime.h>
#include <cuda_fp16.h>
#include <cstdint>

#define EMBD  1024
#define NH    16
#define DH    64
#define BATCH 2
#define SEQ   2048
#define MROWS 4096
#define KDIM  1024

// ---------------- scratch (device globals: allocation-free) ----------------
__device__ __align__(16) __half g_xh[MROWS*KDIM];
__device__ __align__(16) __half g_wih[3*EMBD*KDIM];
__device__ __align__(16) __half g_woh[EMBD*KDIM];
__device__ __align__(16) __half g_qh[BATCH*NH*SEQ*DH];
__device__ __align__(16) __half g_kh[BATCH*NH*SEQ*DH];
__device__ __align__(16) __half g_vh[BATCH*NH*SEQ*DH];
__device__ __align__(16) __half g_ah[MROWS*EMBD];
__device__ __align__(16) __half g_al[MROWS*EMBD];

// ---------------- PTX helpers (sm_80-level: valid under compute_103) -------
__device__ __forceinline__ uint32_t smem_u32(const void* p) {
    uint32_t a;
    asm("{ .reg .u64 t; cvta.to.shared.u64 t, %1; cvt.u32.u64 %0, t; }" : "=r"(a) : "l"(p));
    return a;
}
#define CPA16(dst, src) asm volatile("cp.async.cg.shared.global [%0], [%1], 16;" :: "r"(dst), "l"(src))
#define CPC()   asm volatile("cp.async.commit_group;" ::: "memory")
#define CPW(n)  asm volatile("cp.async.wait_group %0;" :: "n"(n) : "memory")

#define LDSM4(r0,r1,r2,r3,a) \
    asm volatile("ldmatrix.sync.aligned.m8n8.x4.shared.b16 {%0,%1,%2,%3}, [%4];" \
        : "=r"(r0),"=r"(r1),"=r"(r2),"=r"(r3) : "r"(a))
#define LDSM2(r0,r1,a) \
    asm volatile("ldmatrix.sync.aligned.m8n8.x2.shared.b16 {%0,%1}, [%2];" \
        : "=r"(r0),"=r"(r1) : "r"(a))
#define LDSM2T(r0,r1,a) \
    asm volatile("ldmatrix.sync.aligned.m8n8.x2.trans.shared.b16 {%0,%1}, [%2];" \
        : "=r"(r0),"=r"(r1) : "r"(a))

#define MMA(d, a, b) \
    asm volatile("mma.sync.aligned.m16n8k16.row.col.f32.f16.f16.f32 " \
        "{%0,%1,%2,%3},{%4,%5,%6,%7},{%8,%9},{%0,%1,%2,%3};" \
        : "+f"((d)[0]),"+f"((d)[1]),"+f"((d)[2]),"+f"((d)[3]) \
        : "r"((a)[0]),"r"((a)[1]),"r"((a)[2]),"r"((a)[3]),"r"((b)[0]),"r"((b)[1]))

__device__ __forceinline__ uint32_t packh2(float a, float b) {
    __half2 h = __halves2half2(__float2half_rn(a), __float2half_rn(b));
    return *reinterpret_cast<uint32_t*>(&h);
}

// ---------------- fp32 -> fp16 converts ----------------
__global__ __launch_bounds__(256)
void cvt_hi_kernel(const float* __restrict__ s, __half* __restrict__ hi, int n4)
{
    int i = blockIdx.x * 256 + threadIdx.x;
    if (i >= n4) return;
    float4 v = ((const float4*)s)[i];
    ((__half2*)hi)[2*i]   = __halves2half2(__float2half_rn(v.x), __float2half_rn(v.y));
    ((__half2*)hi)[2*i+1] = __halves2half2(__float2half_rn(v.z), __float2half_rn(v.w));
}

// ============================================================================
// HMMA NT GEMM: C = (Ah[+Al])[M,K] * Bh[N,K]^T, K=1024.
// mode 0 (QKV): 1-term (all bands; noise lands on softmax-averaged paths).
// mode 1 (out-proj): 2-term A split (deterministic path anchor).
// BK=64, 3-stage cp.async pipeline. 16 warps (4x4), warp tile 32x32.
// Rows 64 halves data + 8 pad = 144B (conflict-free ldmatrix).
// ============================================================================
#define GROW   144              // bytes per smem row
#define GTILE  (128*GROW)       // 18432 B per tile
#define GSTG   (3*GTILE)        // 55296 B per stage (Ah, Al, Bh)
#define GSMEM  (3*GSTG)         // 165888 B

__global__ __launch_bounds__(512, 1)
void gemm_tc(const __half* __restrict__ Ah, const __half* __restrict__ Al,
             const __half* __restrict__ Bh,
             const float* __restrict__ bias, float* __restrict__ outp, int mode)
{
    extern __shared__ char smg[];
    const uint32_t smb = smem_u32(smg);
    const int tid = threadIdx.x, lane = tid & 31, wid = tid >> 5;
    const int wm = wid >> 2, wn = wid & 3;          // 4 x 4 warp grid
    const int m0 = blockIdx.y * 128, n0 = blockIdx.x * 128;
    const bool use_al = (mode != 0);                 // 2-term only for out-proj

    const __half* srcs[3] = {Ah, Al, Bh};

    auto issue_stage = [&](int kt, int st) {
        #pragma unroll
        for (int it = 0; it < 6; ++it) {
            int idx = it * 512 + tid;           // 0..3071
            int tile = idx >> 10;               // 0..2
            if (tile == 1 && !use_al) continue;
            int t2 = idx & 1023;
            int row = t2 >> 3, seg = t2 & 7;    // 128 rows x 8 16B-segs
            int grow = (tile < 2 ? m0 : n0) + row;
            const __half* src = srcs[tile] + (size_t)grow * KDIM + kt * 64 + seg * 8;
            uint32_t dst = smb + st * GSTG + tile * GTILE + row * GROW + seg * 16;
            CPA16(dst, src);
        }
    };

    float acc[2][4][4];
    #pragma unroll
    for (int i = 0; i < 2; i++)
        #pragma unroll
        for (int j = 0; j < 4; j++)
            #pragma unroll
            for (int r = 0; r < 4; r++) acc[i][j][r] = 0.f;

    issue_stage(0, 0); CPC();
    issue_stage(1, 1); CPC();

    const int NK = KDIM / 64;
    for (int kt = 0; kt < NK; ++kt) {
        CPW(1);
        __syncthreads();
        if (kt + 2 < NK) { issue_stage(kt + 2, (kt + 2) % 3); CPC(); }

        const uint32_t base = smb + (kt % 3) * GSTG;
        #pragma unroll
        for (int ks = 0; ks < 4; ++ks) {
            uint32_t a_h[2][4], a_l[2][4];
            const int acol = ks * 16 + ((lane >> 4) << 3);
            #pragma unroll
            for (int i = 0; i < 2; ++i) {
                int r = wm * 32 + i * 16 + (lane & 15);
                uint32_t ad = base + r * GROW + acol * 2;
                LDSM4(a_h[i][0], a_h[i][1], a_h[i][2], a_h[i][3], ad);
                if (use_al)
                    LDSM4(a_l[i][0], a_l[i][1], a_l[i][2], a_l[i][3], ad + GTILE);
            }
            const int bcol = ks * 16 + (((lane >> 3) & 1) << 3);
            #pragma unroll
            for (int j = 0; j < 4; ++j) {
                int r = wn * 32 + j * 8 + (lane & 7);
                uint32_t bd = base + 2 * GTILE + r * GROW + bcol * 2;
                uint32_t b_h[2];
                LDSM2(b_h[0], b_h[1], bd);
                #pragma unroll
                for (int i = 0; i < 2; ++i) {
                    MMA(acc[i][j], a_h[i], b_h);
                    if (use_al) MMA(acc[i][j], a_l[i], b_h);
                }
            }
        }
    }

    // ---------------- epilogue ----------------
    const int g = lane >> 2, tg = lane & 3;
    if (mode == 0) {
        const int sel = n0 >> 10;                    // 0=q 1=k 2=v
        __half* dh = (sel == 0) ? g_qh : (sel == 1) ? g_kh : g_vh;
        #pragma unroll
        for (int i = 0; i < 2; ++i) {
            #pragma unroll
            for (int j = 0; j < 4; ++j) {
                int n = n0 + wn * 32 + j * 8 + tg * 2;
                int hh = (n & 1023) >> 6, dd = n & 63;
                float b0 = __ldg(bias + n), b1 = __ldg(bias + n + 1);
                #pragma unroll
                for (int rr = 0; rr < 2; ++rr) {
                    int m = m0 + wm * 32 + i * 16 + g + rr * 8;
                    int bb = m >> 11, ss = m & 2047;
                    float v0 = acc[i][j][rr*2+0] + b0;
                    float v1 = acc[i][j][rr*2+1] + b1;
                    size_t o = (((size_t)(bb * NH + hh)) * SEQ + ss) * DH + dd;
                    *(__half2*)&dh[o] = __halves2half2(__float2half_rn(v0),
                                                       __float2half_rn(v1));
                }
            }
        }
    } else {
        #pragma unroll
        for (int i = 0; i < 2; ++i) {
            #pragma unroll
            for (int j = 0; j < 4; ++j) {
                int n = n0 + wn * 32 + j * 8 + tg * 2;
                float b0 = __ldg(bias + n), b1 = __ldg(bias + n + 1);
                #pragma unroll
                for (int rr = 0; rr < 2; ++rr) {
                    int m = m0 + wm * 32 + i * 16 + g + rr * 8;
                    float2 w;
                    w.x = acc[i][j][rr*2+0] + b0;
                    w.y = acc[i][j][rr*2+1] + b1;
                    *(float2*)&outp[(size_t)m * EMBD + n] = w;
                }
            }
        }
    }
}

// ============================================================================
// Flash attention, HMMA single-term. CTA = 256 q-rows of one (b,h);
// 8 warps x two 16-row blocks. Q FRAGMENTS PERSIST IN REGISTERS (loaded
// once — Q is invariant across the KV loop; kills 16 LDSM4/warp/iter).
// KV staged 128 rows per cp.async stage (2 x 64-row passes per barrier pair).
// S = Qh Kh^T ; O += Ph Vh.  Output kept 2-term (hi+lo) for out-proj.
// smem half-stride 72 (144B rows): conflict-free ldmatrix (incl. trans).
// ============================================================================
#define QROWS  256
#define QTILE  (QROWS*72)      // halves for Qh
#define KVHALF 4608            // 64*72 halves (one 64-row sub-tile)
#define KVTILE (2*KVHALF)      // 128*72 halves per K or V tile
#define KVBUF  (2*KVTILE)      // Kh, Vh
#define ASMEM  ((QTILE + 2*KVBUF) * 2)   // bytes = 110592

__global__ __launch_bounds__(256, 1)
void attn_mma()
{
    extern __shared__ __half smh[];
    const uint32_t smb = smem_u32(smh);
    const int tid = threadIdx.x, lane = tid & 31, w = tid >> 5;
    const int g = lane >> 2, tg = lane & 3;
    const int bh = blockIdx.y;
    const int q0 = blockIdx.x * QROWS;
    const size_t hb = (size_t)bh * SEQ * DH;

    const uint32_t KV_o = QTILE;

    // ---- prologue: Qh (256 rows) then KV stages 0,1 (128 rows each)
    #pragma unroll
    for (int it = 0; it < 8; ++it) {
        int idx = it * 256 + tid;              // 0..2047
        int row = idx >> 3, seg = idx & 7;
        const __half* src = g_qh + hb + (size_t)(q0 + row) * DH + seg * 8;
        CPA16(smb + (row * 72 + seg * 8) * 2, src);
    }
    const __half* kvsrc[2] = {g_kh, g_vh};
    auto issue_kv = [&](int kt2, int b) {
        #pragma unroll
        for (int it = 0; it < 8; ++it) {
            int idx = it * 256 + tid;          // 0..2047
            int tile = idx >> 10;              // 0: Kh, 1: Vh
            int t2 = idx & 1023;
            int row = t2 >> 3, seg = t2 & 7;   // 128 rows x 8 segs
            const __half* src = kvsrc[tile] + hb + (size_t)(kt2 * 128 + row) * DH + seg * 8;
            uint32_t dst = smb + (KV_o + b * KVBUF + tile * KVTILE + row * 72 + seg * 8) * 2;
            CPA16(dst, src);
        }
    };
    CPC();                      // group0 = Q
    issue_kv(0, 0); CPC();      // group1 = kv0
    issue_kv(1, 1); CPC();      // group2 = kv1

    // ---- hoist Q fragments into registers (Q smem never re-read) ----
    uint32_t qf0[4][4], qf1[4][4];
    CPW(2);                     // Q (group0) complete
    __syncthreads();
    #pragma unroll
    for (int ds = 0; ds < 4; ++ds) {
        int col = ds * 16 + ((lane >> 4) << 3);
        int r0 = w * 16 + (lane & 15);
        int r1 = 128 + w * 16 + (lane & 15);
        LDSM4(qf0[ds][0], qf0[ds][1], qf0[ds][2], qf0[ds][3], smb + (r0 * 72 + col) * 2);
        LDSM4(qf1[ds][0], qf1[ds][1], qf1[ds][2], qf1[ds][3], smb + (r1 * 72 + col) * 2);
    }

    float o0[8][4], o1[8][4], m0_[2], m1_[2], l0_[2], l1_[2];
    #pragma unroll
    for (int j = 0; j < 8; j++)
        #pragma unroll
        for (int r = 0; r < 4; r++) { o0[j][r] = 0.f; o1[j][r] = 0.f; }
    m0_[0] = m0_[1] = m1_[0] = m1_[1] = __int_as_float(0xff800000);
    l0_[0] = l0_[1] = l1_[0] = l1_[1] = 0.f;

    const int NT2 = SEQ / 128;
    for (int kt2 = 0; kt2 < NT2; ++kt2) {
        const int b = kt2 & 1;
        const uint32_t kvb = KV_o + b * KVBUF;
        CPW(1);
        __syncthreads();

        #pragma unroll
        for (int half = 0; half < 2; ++half) {
            const uint32_t kb = kvb + half * KVHALF;            // K sub-tile
            const uint32_t vb = kvb + KVTILE + half * KVHALF;   // V sub-tile

            // ---- S = Qh Kh^T for both row blocks (Q from registers) ----
            float s0[8][4], s1[8][4];
            #pragma unroll
            for (int j = 0; j < 8; j++)
                #pragma unroll
                for (int r = 0; r < 4; r++) { s0[j][r] = 0.f; s1[j][r] = 0.f; }

            #pragma unroll
            for (int ds = 0; ds < 4; ++ds) {
                int bcol = ds * 16 + (((lane >> 3) & 1) << 3);
                #pragma unroll
                for (int j = 0; j < 8; ++j) {
                    int r = j * 8 + (lane & 7);
                    uint32_t kd = smb + (kb + r * 72 + bcol) * 2;
                    uint32_t kh2[2];
                    LDSM2(kh2[0], kh2[1], kd);
                    MMA(s0[j], qf0[ds], kh2);
                    MMA(s1[j], qf1[ds], kh2);
                }
            }

            // ---- online softmax for both row blocks ----
            #pragma unroll
            for (int rb = 0; rb < 2; ++rb) {
                float (*s)[4] = rb ? s1 : s0;
                float (*o)[4] = rb ? o1 : o0;
                float* m_ = rb ? m1_ : m0_;
                float* l_ = rb ? l1_ : l0_;
                #pragma unroll
                for (int rr = 0; rr < 2; ++rr) {
                    float mx = m_[rr];
                    #pragma unroll
                    for (int j = 0; j < 8; ++j) {
                        float v0 = s[j][rr*2+0] * 0.125f, v1 = s[j][rr*2+1] * 0.125f;
                        s[j][rr*2+0] = v0; s[j][rr*2+1] = v1;
                        mx = fmaxf(mx, fmaxf(v0, v1));
                    }
                    mx = fmaxf(mx, __shfl_xor_sync(0xffffffffu, mx, 1));
                    mx = fmaxf(mx, __shfl_xor_sync(0xffffffffu, mx, 2));
                    float alpha = __expf(m_[rr] - mx);
                    m_[rr] = mx;
                    float rs = 0.f;
                    #pragma unroll
                    for (int j = 0; j < 8; ++j) {
                        float e0 = __expf(s[j][rr*2+0] - mx);
                        float e1 = __expf(s[j][rr*2+1] - mx);
                        s[j][rr*2+0] = e0; s[j][rr*2+1] = e1;
                        rs += e0 + e1;
                    }
                    rs += __shfl_xor_sync(0xffffffffu, rs, 1);
                    rs += __shfl_xor_sync(0xffffffffu, rs, 2);
                    l_[rr] = l_[rr] * alpha + rs;
                    #pragma unroll
                    for (int j = 0; j < 8; ++j) {
                        o[j][rr*2+0] *= alpha;
                        o[j][rr*2+1] *= alpha;
                    }
                }
            }

            // ---- O += Ph Vh ----
            #pragma unroll
            for (int ks = 0; ks < 4; ++ks) {
                uint32_t pa0h[4], pa1h[4];
                #pragma unroll
                for (int hi = 0; hi < 2; ++hi) {
                    float* f0 = s0[ks * 2 + hi];
                    float* f1 = s1[ks * 2 + hi];
                    #pragma unroll
                    for (int q = 0; q < 2; ++q) {
                        pa0h[hi*2+q] = packh2(f0[q*2+0], f0[q*2+1]);
                        pa1h[hi*2+q] = packh2(f1[q*2+0], f1[q*2+1]);
                    }
                }
                int vrow = ks * 16 + (lane & 15);
                #pragma unroll
                for (int jn = 0; jn < 8; ++jn) {
                    uint32_t vd = smb + (vb + vrow * 72 + jn * 8) * 2;
                    uint32_t vh2[2];
                    LDSM2T(vh2[0], vh2[1], vd);
                    MMA(o0[jn], pa0h, vh2);
                    MMA(o1[jn], pa1h, vh2);
                }
            }
        }

        __syncthreads();
        if (kt2 + 2 < NT2) { issue_kv(kt2 + 2, b); CPC(); }
    }

    // ---- epilogue: normalize, split fp16 (hi+lo kept for out-proj) ----
    const int bb = bh >> 4, hh = bh & 15;
    #pragma unroll
    for (int rb = 0; rb < 2; ++rb) {
        float (*o)[4] = rb ? o1 : o0;
        float* l_ = rb ? l1_ : l0_;
        #pragma unroll
        for (int rr = 0; rr < 2; ++rr) {
            float inv = 1.0f / l_[rr];
            int sq = q0 + rb * 128 + w * 16 + g + rr * 8;
            size_t rowo = ((size_t)(bb * SEQ + sq)) * EMBD + hh * DH;
            #pragma unroll
            for (int jn = 0; jn < 8; ++jn) {
                int dd = jn * 8 + tg * 2;
                float v0 = o[jn][rr*2+0] * inv;
                float v1 = o[jn][rr*2+1] * inv;
                __half h0 = __float2half_rn(v0), h1 = __float2half_rn(v1);
                *(__half2*)&g_ah[rowo + dd] = __halves2half2(h0, h1);
                *(__half2*)&g_al[rowo + dd] = __halves2half2(
                    __float2half_rn(v0 - __half2float(h0)),
                    __float2half_rn(v1 - __half2float(h1)));
            }
        }
    }
}

// ============================================================================
extern "C" void kernel_launch(void* const* d_in, const int* in_sizes, int n_in,
                              void* d_out, int out_size)
{
    const float* x     = (const float*)d_in[0];
    const float* W_in  = (const float*)d_in[1];
    const float* b_in  = (const float*)d_in[2];
    const float* W_out = (const float*)d_in[3];
    const float* b_out = (const float*)d_in[4];
    float* out = (float*)d_out;

    cudaFuncSetAttribute(gemm_tc, cudaFuncAttributeMaxDynamicSharedMemorySize, GSMEM);
    cudaFuncSetAttribute(attn_mma, cudaFuncAttributeMaxDynamicSharedMemorySize, ASMEM);

    __half *xh, *wih, *woh, *ah, *al;
    cudaGetSymbolAddress((void**)&xh,  g_xh);
    cudaGetSymbolAddress((void**)&wih, g_wih);
    cudaGetSymbolAddress((void**)&woh, g_woh);
    cudaGetSymbolAddress((void**)&ah,  g_ah);
    cudaGetSymbolAddress((void**)&al,  g_al);

    // fp32 -> fp16 converts (all hi-only; out-proj's 2-term split comes
    // from the attention epilogue's g_ah/g_al)
    cvt_hi_kernel<<<(MROWS*KDIM/4)/256, 256>>>(x, xh, MROWS*KDIM/4);
    cvt_hi_kernel<<<(3*EMBD*KDIM/4)/256, 256>>>(W_in, wih, 3*EMBD*KDIM/4);
    cvt_hi_kernel<<<(EMBD*KDIM/4)/256, 256>>>(W_out, woh, EMBD*KDIM/4);

    // QKV: 1-term: [4096,3072] = Xh @ W_in^T + b_in -> scatter q/k/v (hi)
    gemm_tc<<<dim3(3072/128, MROWS/128), 512, GSMEM>>>(xh, nullptr, wih, b_in, nullptr, 0);

    // flash attention (HMMA, 1-term, Q frags in registers)
    attn_mma<<<dim3(SEQ/QROWS, BATCH*NH), 256, ASMEM>>>();

    // out-proj: 2-term: [4096,1024] = (Ah+Al) @ W_out^T + b_out
    gemm_tc<<<dim3(EMBD/128, MROWS/128), 512, GSMEM>>>(ah, al, woh, b_out, out, 1);
}

// round 15
// speedup vs baseline: 1.5134x; 1.5134x over previous
#include <cuda_runtime.h>
#include <cuda_fp16.h>
#include <cstdint>

#define EMBD  1024
#define NH    16
#define DH    64
#define BATCH 2
#define SEQ   2048
#define MROWS 4096
#define KDIM  1024

// ---------------- scratch (device globals: allocation-free) ----------------
__device__ __align__(16) __half g_xh[MROWS*KDIM];
__device__ __align__(16) __half g_xl[MROWS*KDIM];
__device__ __align__(16) __half g_wih[3*EMBD*KDIM];
__device__ __align__(16) __half g_woh[EMBD*KDIM];
__device__ __align__(16) __half g_qh[BATCH*NH*SEQ*DH];
__device__ __align__(16) __half g_kh[BATCH*NH*SEQ*DH];
__device__ __align__(16) __half g_vh[BATCH*NH*SEQ*DH];
__device__ __align__(16) __half g_ah[MROWS*EMBD];
__device__ __align__(16) __half g_al[MROWS*EMBD];

// ---------------- PTX helpers (sm_80-level: valid under compute_103) -------
__device__ __forceinline__ uint32_t smem_u32(const void* p) {
    uint32_t a;
    asm("{ .reg .u64 t; cvta.to.shared.u64 t, %1; cvt.u32.u64 %0, t; }" : "=r"(a) : "l"(p));
    return a;
}
#define CPA16(dst, src) asm volatile("cp.async.cg.shared.global [%0], [%1], 16;" :: "r"(dst), "l"(src))
#define CPC()   asm volatile("cp.async.commit_group;" ::: "memory")
#define CPW(n)  asm volatile("cp.async.wait_group %0;" :: "n"(n) : "memory")

#define LDSM4(r0,r1,r2,r3,a) \
    asm volatile("ldmatrix.sync.aligned.m8n8.x4.shared.b16 {%0,%1,%2,%3}, [%4];" \
        : "=r"(r0),"=r"(r1),"=r"(r2),"=r"(r3) : "r"(a))
#define LDSM2(r0,r1,a) \
    asm volatile("ldmatrix.sync.aligned.m8n8.x2.shared.b16 {%0,%1}, [%2];" \
        : "=r"(r0),"=r"(r1) : "r"(a))
#define LDSM2T(r0,r1,a) \
    asm volatile("ldmatrix.sync.aligned.m8n8.x2.trans.shared.b16 {%0,%1}, [%2];" \
        : "=r"(r0),"=r"(r1) : "r"(a))

#define MMA(d, a, b) \
    asm volatile("mma.sync.aligned.m16n8k16.row.col.f32.f16.f16.f32 " \
        "{%0,%1,%2,%3},{%4,%5,%6,%7},{%8,%9},{%0,%1,%2,%3};" \
        : "+f"((d)[0]),"+f"((d)[1]),"+f"((d)[2]),"+f"((d)[3]) \
        : "r"((a)[0]),"r"((a)[1]),"r"((a)[2]),"r"((a)[3]),"r"((b)[0]),"r"((b)[1]))

__device__ __forceinline__ uint32_t packh2(float a, float b) {
    __half2 h = __halves2half2(__float2half_rn(a), __float2half_rn(b));
    return *reinterpret_cast<uint32_t*>(&h);
}

// ---------------- fp32 -> fp16 hi/lo split ----------------
__global__ __launch_bounds__(256)
void cvt_kernel(const float* __restrict__ s, __half* __restrict__ hi,
                __half* __restrict__ lo, int n4)
{
    int i = blockIdx.x * 256 + threadIdx.x;
    if (i >= n4) return;
    float4 v = ((const float4*)s)[i];
    __half h0 = __float2half_rn(v.x), h1 = __float2half_rn(v.y);
    __half h2 = __float2half_rn(v.z), h3 = __float2half_rn(v.w);
    ((__half2*)hi)[2*i]   = __halves2half2(h0, h1);
    ((__half2*)hi)[2*i+1] = __halves2half2(h2, h3);
    ((__half2*)lo)[2*i]   = __halves2half2(
        __float2half_rn(v.x - __half2float(h0)), __float2half_rn(v.y - __half2float(h1)));
    ((__half2*)lo)[2*i+1] = __halves2half2(
        __float2half_rn(v.z - __half2float(h2)), __float2half_rn(v.w - __half2float(h3)));
}

__global__ __launch_bounds__(256)
void cvt_hi_kernel(const float* __restrict__ s, __half* __restrict__ hi, int n4)
{
    int i = blockIdx.x * 256 + threadIdx.x;
    if (i >= n4) return;
    float4 v = ((const float4*)s)[i];
    ((__half2*)hi)[2*i]   = __halves2half2(__float2half_rn(v.x), __float2half_rn(v.y));
    ((__half2*)hi)[2*i+1] = __halves2half2(__float2half_rn(v.z), __float2half_rn(v.w));
}

// ============================================================================
// HMMA NT GEMM: C = (Ah[+Al])[M,K] * Bh[N,K]^T, K=1024.
// mode 0 (QKV): Q band (sel==0) uses 2-term A split; K/V bands 1-term
//               (their noise enters only softmax-averaged paths).
// mode 1 (out-proj): always 2-term.
// BK=64, 3-stage cp.async pipeline. 16 warps (4x4), warp tile 32x32.
// Rows 64 halves data + 8 pad = 144B (conflict-free ldmatrix).
// ============================================================================
#define GROW   144              // bytes per smem row
#define GTILE  (128*GROW)       // 18432 B per tile
#define GSTG   (3*GTILE)        // 55296 B per stage (Ah, Al, Bh)
#define GSMEM  (3*GSTG)         // 165888 B

__global__ __launch_bounds__(512, 1)
void gemm_tc(const __half* __restrict__ Ah, const __half* __restrict__ Al,
             const __half* __restrict__ Bh,
             const float* __restrict__ bias, float* __restrict__ outp, int mode)
{
    extern __shared__ char smg[];
    const uint32_t smb = smem_u32(smg);
    const int tid = threadIdx.x, lane = tid & 31, wid = tid >> 5;
    const int wm = wid >> 2, wn = wid & 3;          // 4 x 4 warp grid
    const int m0 = blockIdx.y * 128, n0 = blockIdx.x * 128;
    const int sel = n0 >> 10;                        // QKV band: 0=q 1=k 2=v
    const bool use_al = (mode != 0) || (sel == 0);   // 2-term only where needed

    const __half* srcs[3] = {Ah, Al, Bh};

    auto issue_stage = [&](int kt, int st) {
        #pragma unroll
        for (int it = 0; it < 6; ++it) {
            int idx = it * 512 + tid;           // 0..3071
            int tile = idx >> 10;               // 0..2
            if (tile == 1 && !use_al) continue;
            int t2 = idx & 1023;
            int row = t2 >> 3, seg = t2 & 7;    // 128 rows x 8 16B-segs
            int grow = (tile < 2 ? m0 : n0) + row;
            const __half* src = srcs[tile] + (size_t)grow * KDIM + kt * 64 + seg * 8;
            uint32_t dst = smb + st * GSTG + tile * GTILE + row * GROW + seg * 16;
            CPA16(dst, src);
        }
    };

    float acc[2][4][4];
    #pragma unroll
    for (int i = 0; i < 2; i++)
        #pragma unroll
        for (int j = 0; j < 4; j++)
            #pragma unroll
            for (int r = 0; r < 4; r++) acc[i][j][r] = 0.f;

    issue_stage(0, 0); CPC();
    issue_stage(1, 1); CPC();

    const int NK = KDIM / 64;
    for (int kt = 0; kt < NK; ++kt) {
        CPW(1);
        __syncthreads();
        if (kt + 2 < NK) { issue_stage(kt + 2, (kt + 2) % 3); CPC(); }

        const uint32_t base = smb + (kt % 3) * GSTG;
        #pragma unroll
        for (int ks = 0; ks < 4; ++ks) {
            uint32_t a_h[2][4], a_l[2][4];
            const int acol = ks * 16 + ((lane >> 4) << 3);
            #pragma unroll
            for (int i = 0; i < 2; ++i) {
                int r = wm * 32 + i * 16 + (lane & 15);
                uint32_t ad = base + r * GROW + acol * 2;
                LDSM4(a_h[i][0], a_h[i][1], a_h[i][2], a_h[i][3], ad);
                if (use_al)
                    LDSM4(a_l[i][0], a_l[i][1], a_l[i][2], a_l[i][3], ad + GTILE);
            }
            const int bcol = ks * 16 + (((lane >> 3) & 1) << 3);
            #pragma unroll
            for (int j = 0; j < 4; ++j) {
                int r = wn * 32 + j * 8 + (lane & 7);
                uint32_t bd = base + 2 * GTILE + r * GROW + bcol * 2;
                uint32_t b_h[2];
                LDSM2(b_h[0], b_h[1], bd);
                #pragma unroll
                for (int i = 0; i < 2; ++i) {
                    MMA(acc[i][j], a_h[i], b_h);
                    if (use_al) MMA(acc[i][j], a_l[i], b_h);
                }
            }
        }
    }

    // ---------------- epilogue ----------------
    const int g = lane >> 2, tg = lane & 3;
    if (mode == 0) {
        __half* dh = (sel == 0) ? g_qh : (sel == 1) ? g_kh : g_vh;
        #pragma unroll
        for (int i = 0; i < 2; ++i) {
            #pragma unroll
            for (int j = 0; j < 4; ++j) {
                int n = n0 + wn * 32 + j * 8 + tg * 2;
                int hh = (n & 1023) >> 6, dd = n & 63;
                float b0 = __ldg(bias + n), b1 = __ldg(bias + n + 1);
                #pragma unroll
                for (int rr = 0; rr < 2; ++rr) {
                    int m = m0 + wm * 32 + i * 16 + g + rr * 8;
                    int bb = m >> 11, ss = m & 2047;
                    float v0 = acc[i][j][rr*2+0] + b0;
                    float v1 = acc[i][j][rr*2+1] + b1;
                    size_t o = (((size_t)(bb * NH + hh)) * SEQ + ss) * DH + dd;
                    *(__half2*)&dh[o] = __halves2half2(__float2half_rn(v0),
                                                       __float2half_rn(v1));
                }
            }
        }
    } else {
        #pragma unroll
        for (int i = 0; i < 2; ++i) {
            #pragma unroll
            for (int j = 0; j < 4; ++j) {
                int n = n0 + wn * 32 + j * 8 + tg * 2;
                float b0 = __ldg(bias + n), b1 = __ldg(bias + n + 1);
                #pragma unroll
                for (int rr = 0; rr < 2; ++rr) {
                    int m = m0 + wm * 32 + i * 16 + g + rr * 8;
                    float2 w;
                    w.x = acc[i][j][rr*2+0] + b0;
                    w.y = acc[i][j][rr*2+1] + b1;
                    *(float2*)&outp[(size_t)m * EMBD + n] = w;
                }
            }
        }
    }
}

// ============================================================================
// Flash attention, HMMA single-term (softmax-averaged noise paths).
// CTA = 256 q-rows of one (b,h); 8 warps x two 16-row blocks.
// KV staged 128 rows per cp.async stage (2 x 64-row passes per barrier pair).
// S = Qh Kh^T ; O += Ph Vh.  Output kept 2-term (hi+lo) for out-proj.
// smem half-stride 72 (144B rows): conflict-free ldmatrix (incl. trans).
// ============================================================================
#define QROWS  256
#define QTILE  (QROWS*72)      // halves for Qh
#define KVHALF 4608            // 64*72 halves (one 64-row sub-tile)
#define KVTILE (2*KVHALF)      // 128*72 halves per K or V tile
#define KVBUF  (2*KVTILE)      // Kh, Vh
#define ASMEM  ((QTILE + 2*KVBUF) * 2)   // bytes = 110592

__global__ __launch_bounds__(256, 1)
void attn_mma()
{
    extern __shared__ __half smh[];
    const uint32_t smb = smem_u32(smh);
    const int tid = threadIdx.x, lane = tid & 31, w = tid >> 5;
    const int g = lane >> 2, tg = lane & 3;
    const int bh = blockIdx.y;
    const int q0 = blockIdx.x * QROWS;
    const size_t hb = (size_t)bh * SEQ * DH;

    const uint32_t KV_o = QTILE;

    // ---- prologue: Qh (256 rows) then KV stages 0,1 (128 rows each)
    #pragma unroll
    for (int it = 0; it < 8; ++it) {
        int idx = it * 256 + tid;              // 0..2047
        int row = idx >> 3, seg = idx & 7;
        const __half* src = g_qh + hb + (size_t)(q0 + row) * DH + seg * 8;
        CPA16(smb + (row * 72 + seg * 8) * 2, src);
    }
    const __half* kvsrc[2] = {g_kh, g_vh};
    auto issue_kv = [&](int kt2, int b) {
        #pragma unroll
        for (int it = 0; it < 8; ++it) {
            int idx = it * 256 + tid;          // 0..2047
            int tile = idx >> 10;              // 0: Kh, 1: Vh
            int t2 = idx & 1023;
            int row = t2 >> 3, seg = t2 & 7;   // 128 rows x 8 segs
            const __half* src = kvsrc[tile] + hb + (size_t)(kt2 * 128 + row) * DH + seg * 8;
            uint32_t dst = smb + (KV_o + b * KVBUF + tile * KVTILE + row * 72 + seg * 8) * 2;
            CPA16(dst, src);
        }
    };
    issue_kv(0, 0); CPC();
    issue_kv(1, 1); CPC();

    float o0[8][4], o1[8][4], m0_[2], m1_[2], l0_[2], l1_[2];
    #pragma unroll
    for (int j = 0; j < 8; j++)
        #pragma unroll
        for (int r = 0; r < 4; r++) { o0[j][r] = 0.f; o1[j][r] = 0.f; }
    m0_[0] = m0_[1] = m1_[0] = m1_[1] = __int_as_float(0xff800000);
    l0_[0] = l0_[1] = l1_[0] = l1_[1] = 0.f;

    const int NT2 = SEQ / 128;
    for (int kt2 = 0; kt2 < NT2; ++kt2) {
        const int b = kt2 & 1;
        const uint32_t kvb = KV_o + b * KVBUF;
        CPW(1);
        __syncthreads();

        #pragma unroll
        for (int half = 0; half < 2; ++half) {
            const uint32_t kb = kvb + half * KVHALF;            // K sub-tile
            const uint32_t vb = kvb + KVTILE + half * KVHALF;   // V sub-tile

            // ---- S = Qh Kh^T for both row blocks ----
            float s0[8][4], s1[8][4];
            #pragma unroll
            for (int j = 0; j < 8; j++)
                #pragma unroll
                for (int r = 0; r < 4; r++) { s0[j][r] = 0.f; s1[j][r] = 0.f; }

            #pragma unroll
            for (int ds = 0; ds < 4; ++ds) {
                uint32_t qh0[4], qh1[4];
                {
                    int col = ds * 16 + ((lane >> 4) << 3);
                    int r0 = w * 16 + (lane & 15);
                    int r1 = 128 + w * 16 + (lane & 15);
                    LDSM4(qh0[0], qh0[1], qh0[2], qh0[3], smb + (r0 * 72 + col) * 2);
                    LDSM4(qh1[0], qh1[1], qh1[2], qh1[3], smb + (r1 * 72 + col) * 2);
                }
                int bcol = ds * 16 + (((lane >> 3) & 1) << 3);
                #pragma unroll
                for (int j = 0; j < 8; ++j) {
                    int r = j * 8 + (lane & 7);
                    uint32_t kd = smb + (kb + r * 72 + bcol) * 2;
                    uint32_t kh2[2];
                    LDSM2(kh2[0], kh2[1], kd);
                    MMA(s0[j], qh0, kh2);
                    MMA(s1[j], qh1, kh2);
                }
            }

            // ---- online softmax for both row blocks ----
            #pragma unroll
            for (int rb = 0; rb < 2; ++rb) {
                float (*s)[4] = rb ? s1 : s0;
                float (*o)[4] = rb ? o1 : o0;
                float* m_ = rb ? m1_ : m0_;
                float* l_ = rb ? l1_ : l0_;
                #pragma unroll
                for (int rr = 0; rr < 2; ++rr) {
                    float mx = m_[rr];
                    #pragma unroll
                    for (int j = 0; j < 8; ++j) {
                        float v0 = s[j][rr*2+0] * 0.125f, v1 = s[j][rr*2+1] * 0.125f;
                        s[j][rr*2+0] = v0; s[j][rr*2+1] = v1;
                        mx = fmaxf(mx, fmaxf(v0, v1));
                    }
                    mx = fmaxf(mx, __shfl_xor_sync(0xffffffffu, mx, 1));
                    mx = fmaxf(mx, __shfl_xor_sync(0xffffffffu, mx, 2));
                    float alpha = __expf(m_[rr] - mx);
                    m_[rr] = mx;
                    float rs = 0.f;
                    #pragma unroll
                    for (int j = 0; j < 8; ++j) {
                        float e0 = __expf(s[j][rr*2+0] - mx);
                        float e1 = __expf(s[j][rr*2+1] - mx);
                        s[j][rr*2+0] = e0; s[j][rr*2+1] = e1;
                        rs += e0 + e1;
                    }
                    rs += __shfl_xor_sync(0xffffffffu, rs, 1);
                    rs += __shfl_xor_sync(0xffffffffu, rs, 2);
                    l_[rr] = l_[rr] * alpha + rs;
                    #pragma unroll
                    for (int j = 0; j < 8; ++j) {
                        o[j][rr*2+0] *= alpha;
                        o[j][rr*2+1] *= alpha;
                    }
                }
            }

            // ---- O += Ph Vh (P rounded to fp16; noise averaged by softmax) ----
            #pragma unroll
            for (int ks = 0; ks < 4; ++ks) {
                uint32_t pa0h[4], pa1h[4];
                #pragma unroll
                for (int hi = 0; hi < 2; ++hi) {
                    float* f0 = s0[ks * 2 + hi];
                    float* f1 = s1[ks * 2 + hi];
                    #pragma unroll
                    for (int q = 0; q < 2; ++q) {
                        pa0h[hi*2+q] = packh2(f0[q*2+0], f0[q*2+1]);
                        pa1h[hi*2+q] = packh2(f1[q*2+0], f1[q*2+1]);
                    }
                }
                int vrow = ks * 16 + (lane & 15);
                #pragma unroll
                for (int jn = 0; jn < 8; ++jn) {
                    uint32_t vd = smb + (vb + vrow * 72 + jn * 8) * 2;
                    uint32_t vh2[2];
                    LDSM2T(vh2[0], vh2[1], vd);
                    MMA(o0[jn], pa0h, vh2);
                    MMA(o1[jn], pa1h, vh2);
                }
            }
        }

        __syncthreads();
        if (kt2 + 2 < NT2) { issue_kv(kt2 + 2, b); CPC(); }
    }

    // ---- epilogue: normalize, split fp16 (hi+lo kept for out-proj) ----
    const int bb = bh >> 4, hh = bh & 15;
    #pragma unroll
    for (int rb = 0; rb < 2; ++rb) {
        float (*o)[4] = rb ? o1 : o0;
        float* l_ = rb ? l1_ : l0_;
        #pragma unroll
        for (int rr = 0; rr < 2; ++rr) {
            float inv = 1.0f / l_[rr];
            int sq = q0 + rb * 128 + w * 16 + g + rr * 8;
            size_t rowo = ((size_t)(bb * SEQ + sq)) * EMBD + hh * DH;
            #pragma unroll
            for (int jn = 0; jn < 8; ++jn) {
                int dd = jn * 8 + tg * 2;
                float v0 = o[jn][rr*2+0] * inv;
                float v1 = o[jn][rr*2+1] * inv;
                __half h0 = __float2half_rn(v0), h1 = __float2half_rn(v1);
                *(__half2*)&g_ah[rowo + dd] = __halves2half2(h0, h1);
                *(__half2*)&g_al[rowo + dd] = __halves2half2(
                    __float2half_rn(v0 - __half2float(h0)),
                    __float2half_rn(v1 - __half2float(h1)));
            }
        }
    }
}

// ============================================================================
extern "C" void kernel_launch(void* const* d_in, const int* in_sizes, int n_in,
                              void* d_out, int out_size)
{
    const float* x     = (const float*)d_in[0];
    const float* W_in  = (const float*)d_in[1];
    const float* b_in  = (const float*)d_in[2];
    const float* W_out = (const float*)d_in[3];
    const float* b_out = (const float*)d_in[4];
    float* out = (float*)d_out;

    cudaFuncSetAttribute(gemm_tc, cudaFuncAttributeMaxDynamicSharedMemorySize, GSMEM);
    cudaFuncSetAttribute(attn_mma, cudaFuncAttributeMaxDynamicSharedMemorySize, ASMEM);

    __half *xh, *xl, *wih, *woh, *ah, *al;
    cudaGetSymbolAddress((void**)&xh,  g_xh);
    cudaGetSymbolAddress((void**)&xl,  g_xl);
    cudaGetSymbolAddress((void**)&wih, g_wih);
    cudaGetSymbolAddress((void**)&woh, g_woh);
    cudaGetSymbolAddress((void**)&ah,  g_ah);
    cudaGetSymbolAddress((void**)&al,  g_al);

    // fp32 -> fp16 splits: x full (hi+lo, Q band needs lo), weights hi-only
    cvt_kernel<<<(MROWS*KDIM/4)/256, 256>>>(x, xh, xl, MROWS*KDIM/4);
    cvt_hi_kernel<<<(3*EMBD*KDIM/4)/256, 256>>>(W_in, wih, 3*EMBD*KDIM/4);
    cvt_hi_kernel<<<(EMBD*KDIM/4)/256, 256>>>(W_out, woh, EMBD*KDIM/4);

    // QKV: Q band 2-term, K/V bands 1-term -> scatter q/k/v (hi-only)
    gemm_tc<<<dim3(3072/128, MROWS/128), 512, GSMEM>>>(xh, xl, wih, b_in, nullptr, 0);

    // flash attention (HMMA, single-term S and PV)
    attn_mma<<<dim3(SEQ/QROWS, BATCH*NH), 256, ASMEM>>>();

    // out-proj: 2-term: [4096,1024] = (Ah+Al) @ W_out^T + b_out
    gemm_tc<<<dim3(EMBD/128, MROWS/128), 512, GSMEM>>>(ah, al, woh, b_out, out, 1);
}

// round 17
// speedup vs baseline: 1.5424x; 1.0191x over previous
#include <cuda_runtime.h>
#include <cuda_fp16.h>
#include <cstdint>

#define EMBD  1024
#define NH    16
#define DH    64
#define BATCH 2
#define SEQ   2048
#define MROWS 4096
#define KDIM  1024

// ---------------- scratch (device globals: allocation-free) ----------------
__device__ __align__(16) __half g_xh[MROWS*KDIM];
__device__ __align__(16) __half g_xl[MROWS*KDIM];
__device__ __align__(16) __half g_wih[3*EMBD*KDIM];
__device__ __align__(16) __half g_woh[EMBD*KDIM];
__device__ __align__(16) __half g_qh[BATCH*NH*SEQ*DH];
__device__ __align__(16) __half g_kh[BATCH*NH*SEQ*DH];
__device__ __align__(16) __half g_vh[BATCH*NH*SEQ*DH];
__device__ __align__(16) __half g_ah[MROWS*EMBD];
__device__ __align__(16) __half g_al[MROWS*EMBD];

// ---------------- PTX helpers (sm_80-level: valid under compute_103) -------
__device__ __forceinline__ uint32_t smem_u32(const void* p) {
    uint32_t a;
    asm("{ .reg .u64 t; cvta.to.shared.u64 t, %1; cvt.u32.u64 %0, t; }" : "=r"(a) : "l"(p));
    return a;
}
#define CPA16(dst, src) asm volatile("cp.async.cg.shared.global [%0], [%1], 16;" :: "r"(dst), "l"(src))
#define CPC()   asm volatile("cp.async.commit_group;" ::: "memory")
#define CPW(n)  asm volatile("cp.async.wait_group %0;" :: "n"(n) : "memory")

#define LDSM4(r0,r1,r2,r3,a) \
    asm volatile("ldmatrix.sync.aligned.m8n8.x4.shared.b16 {%0,%1,%2,%3}, [%4];" \
        : "=r"(r0),"=r"(r1),"=r"(r2),"=r"(r3) : "r"(a))
#define LDSM2(r0,r1,a) \
    asm volatile("ldmatrix.sync.aligned.m8n8.x2.shared.b16 {%0,%1}, [%2];" \
        : "=r"(r0),"=r"(r1) : "r"(a))
#define LDSM2T(r0,r1,a) \
    asm volatile("ldmatrix.sync.aligned.m8n8.x2.trans.shared.b16 {%0,%1}, [%2];" \
        : "=r"(r0),"=r"(r1) : "r"(a))

#define MMA(d, a, b) \
    asm volatile("mma.sync.aligned.m16n8k16.row.col.f32.f16.f16.f32 " \
        "{%0,%1,%2,%3},{%4,%5,%6,%7},{%8,%9},{%0,%1,%2,%3};" \
        : "+f"((d)[0]),"+f"((d)[1]),"+f"((d)[2]),"+f"((d)[3]) \
        : "r"((a)[0]),"r"((a)[1]),"r"((a)[2]),"r"((a)[3]),"r"((b)[0]),"r"((b)[1]))

__device__ __forceinline__ uint32_t packh2(float a, float b) {
    __half2 h = __halves2half2(__float2half_rn(a), __float2half_rn(b));
    return *reinterpret_cast<uint32_t*>(&h);
}

// ---------------- fused fp32 -> fp16 converts (one launch) ----------------
// ranges: [0, NX4)            x  -> hi+lo split
//         [NX4, NX4+NWI4)     W_in  -> hi only
//         [.., +NWO4)         W_out -> hi only
#define NX4  (MROWS*KDIM/4)
#define NWI4 (3*EMBD*KDIM/4)
#define NWO4 (EMBD*KDIM/4)

__global__ __launch_bounds__(256)
void cvt_all_kernel(const float* __restrict__ x, const float* __restrict__ Wi,
                    const float* __restrict__ Wo)
{
    int i = blockIdx.x * 256 + threadIdx.x;
    if (i < NX4) {
        float4 v = ((const float4*)x)[i];
        __half h0 = __float2half_rn(v.x), h1 = __float2half_rn(v.y);
        __half h2 = __float2half_rn(v.z), h3 = __float2half_rn(v.w);
        ((__half2*)g_xh)[2*i]   = __halves2half2(h0, h1);
        ((__half2*)g_xh)[2*i+1] = __halves2half2(h2, h3);
        ((__half2*)g_xl)[2*i]   = __halves2half2(
            __float2half_rn(v.x - __half2float(h0)), __float2half_rn(v.y - __half2float(h1)));
        ((__half2*)g_xl)[2*i+1] = __halves2half2(
            __float2half_rn(v.z - __half2float(h2)), __float2half_rn(v.w - __half2float(h3)));
    } else if (i < NX4 + NWI4) {
        int j = i - NX4;
        float4 v = ((const float4*)Wi)[j];
        ((__half2*)g_wih)[2*j]   = __halves2half2(__float2half_rn(v.x), __float2half_rn(v.y));
        ((__half2*)g_wih)[2*j+1] = __halves2half2(__float2half_rn(v.z), __float2half_rn(v.w));
    } else if (i < NX4 + NWI4 + NWO4) {
        int j = i - NX4 - NWI4;
        float4 v = ((const float4*)Wo)[j];
        ((__half2*)g_woh)[2*j]   = __halves2half2(__float2half_rn(v.x), __float2half_rn(v.y));
        ((__half2*)g_woh)[2*j+1] = __halves2half2(__float2half_rn(v.z), __float2half_rn(v.w));
    }
}

// ============================================================================
// HMMA NT GEMM: C = (Ah[+Al])[M,K] * Bh[N,K]^T, K=1024.
// mode 0 (QKV): Q band (sel==0) uses 2-term A split; K/V bands 1-term.
// mode 1 (out-proj): always 2-term.
// BK=64, 3-stage cp.async pipeline. 16 warps (4x4), warp tile 32x32.
// Rows 64 halves data + 8 pad = 144B (conflict-free ldmatrix).
// ============================================================================
#define GROW   144              // bytes per smem row
#define GTILE  (128*GROW)       // 18432 B per tile
#define GSTG   (3*GTILE)        // 55296 B per stage (Ah, Al, Bh)
#define GSMEM  (3*GSTG)         // 165888 B

__global__ __launch_bounds__(512, 1)
void gemm_tc(const __half* __restrict__ Ah, const __half* __restrict__ Al,
             const __half* __restrict__ Bh,
             const float* __restrict__ bias, float* __restrict__ outp, int mode)
{
    extern __shared__ char smg[];
    const uint32_t smb = smem_u32(smg);
    const int tid = threadIdx.x, lane = tid & 31, wid = tid >> 5;
    const int wm = wid >> 2, wn = wid & 3;          // 4 x 4 warp grid
    const int m0 = blockIdx.y * 128, n0 = blockIdx.x * 128;
    const int sel = n0 >> 10;                        // QKV band: 0=q 1=k 2=v
    const bool use_al = (mode != 0) || (sel == 0);   // 2-term only where needed

    const __half* srcs[3] = {Ah, Al, Bh};

    auto issue_stage = [&](int kt, int st) {
        #pragma unroll
        for (int it = 0; it < 6; ++it) {
            int idx = it * 512 + tid;           // 0..3071
            int tile = idx >> 10;               // 0..2
            if (tile == 1 && !use_al) continue;
            int t2 = idx & 1023;
            int row = t2 >> 3, seg = t2 & 7;    // 128 rows x 8 16B-segs
            int grow = (tile < 2 ? m0 : n0) + row;
            const __half* src = srcs[tile] + (size_t)grow * KDIM + kt * 64 + seg * 8;
            uint32_t dst = smb + st * GSTG + tile * GTILE + row * GROW + seg * 16;
            CPA16(dst, src);
        }
    };

    float acc[2][4][4];
    #pragma unroll
    for (int i = 0; i < 2; i++)
        #pragma unroll
        for (int j = 0; j < 4; j++)
            #pragma unroll
            for (int r = 0; r < 4; r++) acc[i][j][r] = 0.f;

    issue_stage(0, 0); CPC();
    issue_stage(1, 1); CPC();

    const int NK = KDIM / 64;
    for (int kt = 0; kt < NK; ++kt) {
        if (kt + 2 < NK) { CPW(1); } else { CPW(0); }   // tail: wait all (sound)
        __syncthreads();
        if (kt + 2 < NK) { issue_stage(kt + 2, (kt + 2) % 3); CPC(); }

        const uint32_t base = smb + (kt % 3) * GSTG;
        #pragma unroll
        for (int ks = 0; ks < 4; ++ks) {
            uint32_t a_h[2][4], a_l[2][4];
            const int acol = ks * 16 + ((lane >> 4) << 3);
            #pragma unroll
            for (int i = 0; i < 2; ++i) {
                int r = wm * 32 + i * 16 + (lane & 15);
                uint32_t ad = base + r * GROW + acol * 2;
                LDSM4(a_h[i][0], a_h[i][1], a_h[i][2], a_h[i][3], ad);
                if (use_al)
                    LDSM4(a_l[i][0], a_l[i][1], a_l[i][2], a_l[i][3], ad + GTILE);
            }
            const int bcol = ks * 16 + (((lane >> 3) & 1) << 3);
            #pragma unroll
            for (int j = 0; j < 4; ++j) {
                int r = wn * 32 + j * 8 + (lane & 7);
                uint32_t bd = base + 2 * GTILE + r * GROW + bcol * 2;
                uint32_t b_h[2];
                LDSM2(b_h[0], b_h[1], bd);
                #pragma unroll
                for (int i = 0; i < 2; ++i) {
                    MMA(acc[i][j], a_h[i], b_h);
                    if (use_al) MMA(acc[i][j], a_l[i], b_h);
                }
            }
        }
    }

    // ---------------- epilogue ----------------
    const int g = lane >> 2, tg = lane & 3;
    if (mode == 0) {
        __half* dh = (sel == 0) ? g_qh : (sel == 1) ? g_kh : g_vh;
        #pragma unroll
        for (int i = 0; i < 2; ++i) {
            #pragma unroll
            for (int j = 0; j < 4; ++j) {
                int n = n0 + wn * 32 + j * 8 + tg * 2;
                int hh = (n & 1023) >> 6, dd = n & 63;
                float b0 = __ldg(bias + n), b1 = __ldg(bias + n + 1);
                #pragma unroll
                for (int rr = 0; rr < 2; ++rr) {
                    int m = m0 + wm * 32 + i * 16 + g + rr * 8;
                    int bb = m >> 11, ss = m & 2047;
                    float v0 = acc[i][j][rr*2+0] + b0;
                    float v1 = acc[i][j][rr*2+1] + b1;
                    size_t o = (((size_t)(bb * NH + hh)) * SEQ + ss) * DH + dd;
                    *(__half2*)&dh[o] = __halves2half2(__float2half_rn(v0),
                                                       __float2half_rn(v1));
                }
            }
        }
    } else {
        #pragma unroll
        for (int i = 0; i < 2; ++i) {
            #pragma unroll
            for (int j = 0; j < 4; ++j) {
                int n = n0 + wn * 32 + j * 8 + tg * 2;
                float b0 = __ldg(bias + n), b1 = __ldg(bias + n + 1);
                #pragma unroll
                for (int rr = 0; rr < 2; ++rr) {
                    int m = m0 + wm * 32 + i * 16 + g + rr * 8;
                    float2 w;
                    w.x = acc[i][j][rr*2+0] + b0;
                    w.y = acc[i][j][rr*2+1] + b1;
                    *(float2*)&outp[(size_t)m * EMBD + n] = w;
                }
            }
        }
    }
}

// ============================================================================
// Flash attention, HMMA single-term. CTA = 256 q-rows of one (b,h);
// 8 warps x two 16-row blocks. KV now 3-STAGE cp.async pipeline
// (128 rows/stage): one __syncthreads per iteration, prefetch issued
// BEFORE compute (a full compute-iteration of load overlap) — the same
// schedule the GEMM has proven. S = Qh Kh^T ; O += Ph Vh.
// Output kept 2-term (hi+lo) for the out-proj's deterministic path.
// smem half-stride 72 (144B rows): conflict-free ldmatrix (incl. trans).
// ============================================================================
#define QROWS  256
#define QTILE  (QROWS*72)      // halves for Qh
#define KVHALF 4608            // 64*72 halves (one 64-row sub-tile)
#define KVTILE (2*KVHALF)      // 128*72 halves per K or V tile
#define KVBUF  (2*KVTILE)      // Kh + Vh per stage
#define NSTG   3
#define ASMEM  ((QTILE + NSTG*KVBUF) * 2)   // bytes = 147456

__global__ __launch_bounds__(256, 1)
void attn_mma()
{
    extern __shared__ __half smh[];
    const uint32_t smb = smem_u32(smh);
    const int tid = threadIdx.x, lane = tid & 31, w = tid >> 5;
    const int g = lane >> 2, tg = lane & 3;
    const int bh = blockIdx.y;
    const int q0 = blockIdx.x * QROWS;
    const size_t hb = (size_t)bh * SEQ * DH;

    const uint32_t KV_o = QTILE;

    // ---- prologue: Qh (256 rows) folded into group0 with kv stage 0
    #pragma unroll
    for (int it = 0; it < 8; ++it) {
        int idx = it * 256 + tid;              // 0..2047
        int row = idx >> 3, seg = idx & 7;
        const __half* src = g_qh + hb + (size_t)(q0 + row) * DH + seg * 8;
        CPA16(smb + (row * 72 + seg * 8) * 2, src);
    }
    const __half* kvsrc[2] = {g_kh, g_vh};
    auto issue_kv = [&](int kt2, int b) {
        #pragma unroll
        for (int it = 0; it < 8; ++it) {
            int idx = it * 256 + tid;          // 0..2047
            int tile = idx >> 10;              // 0: Kh, 1: Vh
            int t2 = idx & 1023;
            int row = t2 >> 3, seg = t2 & 7;   // 128 rows x 8 segs
            const __half* src = kvsrc[tile] + hb + (size_t)(kt2 * 128 + row) * DH + seg * 8;
            uint32_t dst = smb + (KV_o + b * KVBUF + tile * KVTILE + row * 72 + seg * 8) * 2;
            CPA16(dst, src);
        }
    };
    issue_kv(0, 0); CPC();      // group0 = Q + kv0
    issue_kv(1, 1); CPC();      // group1 = kv1

    float o0[8][4], o1[8][4], m0_[2], m1_[2], l0_[2], l1_[2];
    #pragma unroll
    for (int j = 0; j < 8; j++)
        #pragma unroll
        for (int r = 0; r < 4; r++) { o0[j][r] = 0.f; o1[j][r] = 0.f; }
    m0_[0] = m0_[1] = m1_[0] = m1_[1] = __int_as_float(0xff800000);
    l0_[0] = l0_[1] = l1_[0] = l1_[1] = 0.f;

    const int NT2 = SEQ / 128;
    for (int kt2 = 0; kt2 < NT2; ++kt2) {
        const uint32_t kvb = KV_o + (kt2 % NSTG) * KVBUF;
        if (kt2 + 2 < NT2) { CPW(1); } else { CPW(0); }   // tail: wait all
        __syncthreads();
        if (kt2 + 2 < NT2) { issue_kv(kt2 + 2, (kt2 + 2) % NSTG); CPC(); }

        #pragma unroll
        for (int half = 0; half < 2; ++half) {
            const uint32_t kb = kvb + half * KVHALF;            // K sub-tile
            const uint32_t vb = kvb + KVTILE + half * KVHALF;   // V sub-tile

            // ---- S = Qh Kh^T for both row blocks ----
            float s0[8][4], s1[8][4];
            #pragma unroll
            for (int j = 0; j < 8; j++)
                #pragma unroll
                for (int r = 0; r < 4; r++) { s0[j][r] = 0.f; s1[j][r] = 0.f; }

            #pragma unroll
            for (int ds = 0; ds < 4; ++ds) {
                uint32_t qh0[4], qh1[4];
                {
                    int col = ds * 16 + ((lane >> 4) << 3);
                    int r0 = w * 16 + (lane & 15);
                    int r1 = 128 + w * 16 + (lane & 15);
                    LDSM4(qh0[0], qh0[1], qh0[2], qh0[3], smb + (r0 * 72 + col) * 2);
                    LDSM4(qh1[0], qh1[1], qh1[2], qh1[3], smb + (r1 * 72 + col) * 2);
                }
                int bcol = ds * 16 + (((lane >> 3) & 1) << 3);
                #pragma unroll
                for (int j = 0; j < 8; ++j) {
                    int r = j * 8 + (lane & 7);
                    uint32_t kd = smb + (kb + r * 72 + bcol) * 2;
                    uint32_t kh2[2];
                    LDSM2(kh2[0], kh2[1], kd);
                    MMA(s0[j], qh0, kh2);
                    MMA(s1[j], qh1, kh2);
                }
            }

            // ---- online softmax for both row blocks ----
            #pragma unroll
            for (int rb = 0; rb < 2; ++rb) {
                float (*s)[4] = rb ? s1 : s0;
                float (*o)[4] = rb ? o1 : o0;
                float* m_ = rb ? m1_ : m0_;
                float* l_ = rb ? l1_ : l0_;
                #pragma unroll
                for (int rr = 0; rr < 2; ++rr) {
                    float mx = m_[rr];
                    #pragma unroll
                    for (int j = 0; j < 8; ++j) {
                        float v0 = s[j][rr*2+0] * 0.125f, v1 = s[j][rr*2+1] * 0.125f;
                        s[j][rr*2+0] = v0; s[j][rr*2+1] = v1;
                        mx = fmaxf(mx, fmaxf(v0, v1));
                    }
                    mx = fmaxf(mx, __shfl_xor_sync(0xffffffffu, mx, 1));
                    mx = fmaxf(mx, __shfl_xor_sync(0xffffffffu, mx, 2));
                    float alpha = __expf(m_[rr] - mx);
                    m_[rr] = mx;
                    float rs = 0.f;
                    #pragma unroll
                    for (int j = 0; j < 8; ++j) {
                        float e0 = __expf(s[j][rr*2+0] - mx);
                        float e1 = __expf(s[j][rr*2+1] - mx);
                        s[j][rr*2+0] = e0; s[j][rr*2+1] = e1;
                        rs += e0 + e1;
                    }
                    rs += __shfl_xor_sync(0xffffffffu, rs, 1);
                    rs += __shfl_xor_sync(0xffffffffu, rs, 2);
                    l_[rr] = l_[rr] * alpha + rs;
                    #pragma unroll
                    for (int j = 0; j < 8; ++j) {
                        o[j][rr*2+0] *= alpha;
                        o[j][rr*2+1] *= alpha;
                    }
                }
            }

            // ---- O += Ph Vh ----
            #pragma unroll
            for (int ks = 0; ks < 4; ++ks) {
                uint32_t pa0h[4], pa1h[4];
                #pragma unroll
                for (int hi = 0; hi < 2; ++hi) {
                    float* f0 = s0[ks * 2 + hi];
                    float* f1 = s1[ks * 2 + hi];
                    #pragma unroll
                    for (int q = 0; q < 2; ++q) {
                        pa0h[hi*2+q] = packh2(f0[q*2+0], f0[q*2+1]);
                        pa1h[hi*2+q] = packh2(f1[q*2+0], f1[q*2+1]);
                    }
                }
                int vrow = ks * 16 + (lane & 15);
                #pragma unroll
                for (int jn = 0; jn < 8; ++jn) {
                    uint32_t vd = smb + (vb + vrow * 72 + jn * 8) * 2;
                    uint32_t vh2[2];
                    LDSM2T(vh2[0], vh2[1], vd);
                    MMA(o0[jn], pa0h, vh2);
                    MMA(o1[jn], pa1h, vh2);
                }
            }
        }
        // no trailing sync: next iteration's CPW+sync provides the barrier
        // before any buffer in flight is overwritten (3-stage distance).
    }

    // ---- epilogue: normalize, split fp16 (hi+lo kept for out-proj) ----
    const int bb = bh >> 4, hh = bh & 15;
    #pragma unroll
    for (int rb = 0; rb < 2; ++rb) {
        float (*o)[4] = rb ? o1 : o0;
        float* l_ = rb ? l1_ : l0_;
        #pragma unroll
        for (int rr = 0; rr < 2; ++rr) {
            float inv = 1.0f / l_[rr];
            int sq = q0 + rb * 128 + w * 16 + g + rr * 8;
            size_t rowo = ((size_t)(bb * SEQ + sq)) * EMBD + hh * DH;
            #pragma unroll
            for (int jn = 0; jn < 8; ++jn) {
                int dd = jn * 8 + tg * 2;
                float v0 = o[jn][rr*2+0] * inv;
                float v1 = o[jn][rr*2+1] * inv;
                __half h0 = __float2half_rn(v0), h1 = __float2half_rn(v1);
                *(__half2*)&g_ah[rowo + dd] = __halves2half2(h0, h1);
                *(__half2*)&g_al[rowo + dd] = __halves2half2(
                    __float2half_rn(v0 - __half2float(h0)),
                    __float2half_rn(v1 - __half2float(h1)));
            }
        }
    }
}

// ============================================================================
extern "C" void kernel_launch(void* const* d_in, const int* in_sizes, int n_in,
                              void* d_out, int out_size)
{
    const float* x     = (const float*)d_in[0];
    const float* W_in  = (const float*)d_in[1];
    const float* b_in  = (const float*)d_in[2];
    const float* W_out = (const float*)d_in[3];
    const float* b_out = (const float*)d_in[4];
    float* out = (float*)d_out;

    cudaFuncSetAttribute(gemm_tc, cudaFuncAttributeMaxDynamicSharedMemorySize, GSMEM);
    cudaFuncSetAttribute(attn_mma, cudaFuncAttributeMaxDynamicSharedMemorySize, ASMEM);

    __half *xh, *xl, *wih, *woh, *ah, *al;
    cudaGetSymbolAddress((void**)&xh,  g_xh);
    cudaGetSymbolAddress((void**)&xl,  g_xl);
    cudaGetSymbolAddress((void**)&wih, g_wih);
    cudaGetSymbolAddress((void**)&woh, g_woh);
    cudaGetSymbolAddress((void**)&ah,  g_ah);
    cudaGetSymbolAddress((void**)&al,  g_al);

    // fused converts: x (hi+lo) + W_in (hi) + W_out (hi), one launch
    cvt_all_kernel<<<(NX4 + NWI4 + NWO4 + 255) / 256, 256>>>(x, W_in, W_out);

    // QKV: Q band 2-term, K/V bands 1-term -> scatter q/k/v (hi-only)
    gemm_tc<<<dim3(3072/128, MROWS/128), 512, GSMEM>>>(xh, xl, wih, b_in, nullptr, 0);

    // flash attention (HMMA, single-term S and PV, 3-stage KV pipeline)
    attn_mma<<<dim3(SEQ/QROWS, BATCH*NH), 256, ASMEM>>>();

    // out-proj: 2-term: [4096,1024] = (Ah+Al) @ W_out^T + b_out
    gemm_tc<<<dim3(EMBD/128, MROWS/128), 512, GSMEM>>>(ah, al, woh, b_out, out, 1);
}